// round 4
// baseline (speedup 1.0000x reference)
#include <cuda_runtime.h>
#include <cstdint>

#define N_NODES_MAX 100000
#define E_MAX       1600000
#define FEAT_DIM    64
#define SCAN_BLOCK  1024
#define MAX_SCAN_BLOCKS 256

// Zeroed region (one memset): counts, block sums, ready counter.
__device__ int g_counts [N_NODES_MAX];          // in-degree
__device__ int g_sums   [MAX_SCAN_BLOCKS];      // per-block totals
__device__ int g_ctr    [1];                    // scan ready counter
// Not zeroed:
__device__ int g_offsets[N_NODES_MAX];          // excl scan -> row ends after scatter
__device__ int g_csr    [E_MAX];                // src ids grouped by dest

// 1) histogram of destination indices (4 edges/thread, vectorized load)
__global__ void __launch_bounds__(256) hist_kernel(
    const int* __restrict__ dst_idx, int* __restrict__ counts, int E, int N)
{
    int i = blockIdx.x * blockDim.x + threadIdx.x;
    int base = i * 4;
    if (base + 3 < E) {
        int4 d4 = *reinterpret_cast<const int4*>(dst_idx + base);
        if ((unsigned)d4.x < (unsigned)N) atomicAdd(&counts[d4.x], 1);
        if ((unsigned)d4.y < (unsigned)N) atomicAdd(&counts[d4.y], 1);
        if ((unsigned)d4.z < (unsigned)N) atomicAdd(&counts[d4.z], 1);
        if ((unsigned)d4.w < (unsigned)N) atomicAdd(&counts[d4.w], 1);
    } else {
        for (int e = base; e < E; e++) {
            int d = dst_idx[e];
            if ((unsigned)d < (unsigned)N) atomicAdd(&counts[d], 1);
        }
    }
}

// 2) single-kernel global exclusive scan. Requires nb <= #SMs so all blocks
//    are co-resident (nb = 98 for N = 100000).
__global__ void __launch_bounds__(SCAN_BLOCK) scan_kernel(
    const int* __restrict__ counts, int* __restrict__ offsets,
    int* __restrict__ sums, int* __restrict__ ctr, int n, int nb)
{
    __shared__ int sh[SCAN_BLOCK];
    __shared__ int s_base;
    int tid = threadIdx.x;
    int i = blockIdx.x * SCAN_BLOCK + tid;
    int v = (i < n) ? counts[i] : 0;
    sh[tid] = v;
    __syncthreads();
    #pragma unroll
    for (int off = 1; off < SCAN_BLOCK; off <<= 1) {
        int t = (tid >= off) ? sh[tid - off] : 0;
        __syncthreads();
        sh[tid] += t;
        __syncthreads();
    }
    int incl = sh[tid];

    // Publish block total, then wait for all blocks to publish.
    if (tid == SCAN_BLOCK - 1) {
        sums[blockIdx.x] = incl;
        __threadfence();
        atomicAdd(ctr, 1);
    }
    if (tid == 0) {
        while (atomicAdd(ctr, 0) < nb) { }
    }
    __syncthreads();
    __threadfence();

    // Warp 0 computes this block's base = sum of preceding block totals.
    if (tid < 32) {
        int b = 0;
        for (int j = tid; j < blockIdx.x; j += 32) b += sums[j];
        #pragma unroll
        for (int o = 16; o > 0; o >>= 1)
            b += __shfl_down_sync(0xFFFFFFFF, b, o);
        if (tid == 0) s_base = b;
    }
    __syncthreads();

    if (i < n) offsets[i] = s_base + incl - v;   // global exclusive scan
}

// 3) scatter src ids into CSR (offsets become row ends)
__global__ void __launch_bounds__(256) scatter_kernel(
    const int* __restrict__ src_idx, const int* __restrict__ dst_idx,
    int* __restrict__ offsets, int* __restrict__ csr, int E, int N)
{
    int e = blockIdx.x * blockDim.x + threadIdx.x;
    if (e >= E) return;
    int d = dst_idx[e];
    int s = src_idx[e];
    if ((unsigned)d >= (unsigned)N || (unsigned)s >= (unsigned)N) return;
    int pos = atomicAdd(&offsets[d], 1);
    csr[pos] = s;
}

// 4) aggregate + finalize: 16 lanes per dest node, one float4 per lane.
//    out = deg>0 ? 2*feat[node] + sum(feat[src])/deg : feat[node]
__global__ void __launch_bounds__(256) aggregate_kernel(
    const float* __restrict__ feat,
    const int* __restrict__ csr,
    const int* __restrict__ offsets,   // row ends
    const int* __restrict__ counts,    // degrees
    float* __restrict__ out,
    int N)
{
    int t = blockIdx.x * blockDim.x + threadIdx.x;
    int node = t >> 4;
    int lane = t & 15;
    if (node >= N) return;

    int deg = counts[node];
    int end = offsets[node];
    int start = end - deg;
    size_t loff = (size_t)(lane * 4);

    float4 a0 = {0.f,0.f,0.f,0.f}, a1 = {0.f,0.f,0.f,0.f};
    float4 a2 = {0.f,0.f,0.f,0.f}, a3 = {0.f,0.f,0.f,0.f};

    int i = start;
    for (; i + 3 < end; i += 4) {
        int s0 = __ldg(&csr[i]);
        int s1 = __ldg(&csr[i + 1]);
        int s2 = __ldg(&csr[i + 2]);
        int s3 = __ldg(&csr[i + 3]);
        float4 v0 = __ldg(reinterpret_cast<const float4*>(feat + (size_t)s0 * FEAT_DIM + loff));
        float4 v1 = __ldg(reinterpret_cast<const float4*>(feat + (size_t)s1 * FEAT_DIM + loff));
        float4 v2 = __ldg(reinterpret_cast<const float4*>(feat + (size_t)s2 * FEAT_DIM + loff));
        float4 v3 = __ldg(reinterpret_cast<const float4*>(feat + (size_t)s3 * FEAT_DIM + loff));
        a0.x += v0.x; a0.y += v0.y; a0.z += v0.z; a0.w += v0.w;
        a1.x += v1.x; a1.y += v1.y; a1.z += v1.z; a1.w += v1.w;
        a2.x += v2.x; a2.y += v2.y; a2.z += v2.z; a2.w += v2.w;
        a3.x += v3.x; a3.y += v3.y; a3.z += v3.z; a3.w += v3.w;
    }
    for (; i < end; i++) {
        int s0 = __ldg(&csr[i]);
        float4 v0 = __ldg(reinterpret_cast<const float4*>(feat + (size_t)s0 * FEAT_DIM + loff));
        a0.x += v0.x; a0.y += v0.y; a0.z += v0.z; a0.w += v0.w;
    }

    float4 f = __ldg(reinterpret_cast<const float4*>(feat + (size_t)node * FEAT_DIM + loff));
    float4 o;
    if (deg > 0) {
        float inv = 1.0f / (float)deg;
        o.x = 2.0f * f.x + (a0.x + a1.x + a2.x + a3.x) * inv;
        o.y = 2.0f * f.y + (a0.y + a1.y + a2.y + a3.y) * inv;
        o.z = 2.0f * f.z + (a0.z + a1.z + a2.z + a3.z) * inv;
        o.w = 2.0f * f.w + (a0.w + a1.w + a2.w + a3.w) * inv;
    } else {
        o = f;
    }
    *reinterpret_cast<float4*>(out + (size_t)node * FEAT_DIM + loff) = o;
}

extern "C" void kernel_launch(void* const* d_in, const int* in_sizes, int n_in,
                              void* d_out, int out_size)
{
    const float* feat = (const float*)d_in[0];
    const int* edge_index = (const int*)d_in[1];   // int32 (JAX x64-disabled)

    int N = in_sizes[0] / FEAT_DIM;       // 100000
    int E = in_sizes[1] / 2;              // 1600000
    const int* src_idx = edge_index;
    const int* dst_idx = edge_index + E;

    float* out = (float*)d_out;

    void *counts_p, *offsets_p, *sums_p, *ctr_p, *csr_p;
    cudaGetSymbolAddress(&counts_p,  g_counts);
    cudaGetSymbolAddress(&offsets_p, g_offsets);
    cudaGetSymbolAddress(&sums_p,    g_sums);
    cudaGetSymbolAddress(&ctr_p,     g_ctr);
    cudaGetSymbolAddress(&csr_p,     g_csr);
    int* counts  = (int*)counts_p;
    int* offsets = (int*)offsets_p;
    int* sums    = (int*)sums_p;
    int* ctr     = (int*)ctr_p;
    int* csr     = (int*)csr_p;

    // g_counts, g_sums, g_ctr are contiguous in declaration order, but layout
    // isn't guaranteed — zero each explicitly (still one stream op each is
    // avoidable; combine counts+sums+ctr only if contiguous. Be safe: two ops.)
    cudaMemsetAsync(counts, 0, (size_t)N * sizeof(int));
    cudaMemsetAsync(sums, 0, (MAX_SCAN_BLOCKS + 0) * sizeof(int));
    cudaMemsetAsync(ctr, 0, sizeof(int));

    // 1) histogram (4 edges per thread)
    {
        int threads = (E + 3) / 4;
        hist_kernel<<<(threads + 255) / 256, 256>>>(dst_idx, counts, E, N);
    }

    // 2) single-kernel exclusive scan (all blocks co-resident: nb <= 148)
    int nb = (N + SCAN_BLOCK - 1) / SCAN_BLOCK;   // 98
    scan_kernel<<<nb, SCAN_BLOCK>>>(counts, offsets, sums, ctr, N, nb);

    // 3) scatter src ids by dest
    scatter_kernel<<<(E + 255) / 256, 256>>>(src_idx, dst_idx, offsets, csr, E, N);

    // 4) aggregate + finalize
    {
        long long total = (long long)N * 16;
        int grid = (int)((total + 255) / 256);
        aggregate_kernel<<<grid, 256>>>(feat, csr, offsets, counts, out, N);
    }
}

// round 5
// speedup vs baseline: 1.0259x; 1.0259x over previous
#include <cuda_runtime.h>
#include <cstdint>

#define N_NODES_MAX 100000
#define E_MAX       1600000
#define FEAT_DIM    64
#define SCAN_BLOCK  1024
#define MAX_SCAN_BLOCKS 256

__device__ int g_counts [N_NODES_MAX];          // in-degree
__device__ int g_sums   [MAX_SCAN_BLOCKS];      // per-block totals
__device__ int g_ctr    [1];                    // scan ready counter
__device__ int g_offsets[N_NODES_MAX];          // excl scan -> row ends after scatter
__device__ int g_csr    [E_MAX];                // src ids grouped by dest

// 1) histogram of destination indices (4 edges/thread, vectorized load)
__global__ void __launch_bounds__(256) hist_kernel(
    const int* __restrict__ dst_idx, int* __restrict__ counts, int E, int N)
{
    int i = blockIdx.x * blockDim.x + threadIdx.x;
    int base = i * 4;
    if (base + 3 < E) {
        int4 d4 = *reinterpret_cast<const int4*>(dst_idx + base);
        if ((unsigned)d4.x < (unsigned)N) atomicAdd(&counts[d4.x], 1);
        if ((unsigned)d4.y < (unsigned)N) atomicAdd(&counts[d4.y], 1);
        if ((unsigned)d4.z < (unsigned)N) atomicAdd(&counts[d4.z], 1);
        if ((unsigned)d4.w < (unsigned)N) atomicAdd(&counts[d4.w], 1);
    } else {
        for (int e = base; e < E; e++) {
            int d = dst_idx[e];
            if ((unsigned)d < (unsigned)N) atomicAdd(&counts[d], 1);
        }
    }
}

// 2) single-kernel global exclusive scan (all 98 blocks co-resident).
__global__ void __launch_bounds__(SCAN_BLOCK) scan_kernel(
    const int* __restrict__ counts, int* __restrict__ offsets,
    int* __restrict__ sums, int* __restrict__ ctr, int n, int nb)
{
    __shared__ int sh[SCAN_BLOCK];
    __shared__ int s_base;
    int tid = threadIdx.x;
    int i = blockIdx.x * SCAN_BLOCK + tid;
    int v = (i < n) ? counts[i] : 0;
    sh[tid] = v;
    __syncthreads();
    #pragma unroll
    for (int off = 1; off < SCAN_BLOCK; off <<= 1) {
        int t = (tid >= off) ? sh[tid - off] : 0;
        __syncthreads();
        sh[tid] += t;
        __syncthreads();
    }
    int incl = sh[tid];

    if (tid == SCAN_BLOCK - 1) {
        sums[blockIdx.x] = incl;
        __threadfence();
        atomicAdd(ctr, 1);
    }
    if (tid == 0) {
        while (atomicAdd(ctr, 0) < nb) { }
    }
    __syncthreads();
    __threadfence();

    if (tid < 32) {
        int b = 0;
        for (int j = tid; j < blockIdx.x; j += 32) b += sums[j];
        #pragma unroll
        for (int o = 16; o > 0; o >>= 1)
            b += __shfl_down_sync(0xFFFFFFFF, b, o);
        if (tid == 0) s_base = b;
    }
    __syncthreads();

    if (i < n) offsets[i] = s_base + incl - v;
}

// 3) scatter src ids into CSR, 4 edges/thread (offsets become row ends)
__global__ void __launch_bounds__(256) scatter_kernel(
    const int* __restrict__ src_idx, const int* __restrict__ dst_idx,
    int* __restrict__ offsets, int* __restrict__ csr, int E, int N)
{
    int i = blockIdx.x * blockDim.x + threadIdx.x;
    int base = i * 4;
    if (base + 3 < E) {
        int4 s4 = *reinterpret_cast<const int4*>(src_idx + base);
        int4 d4 = *reinterpret_cast<const int4*>(dst_idx + base);
        if ((unsigned)d4.x < (unsigned)N && (unsigned)s4.x < (unsigned)N)
            csr[atomicAdd(&offsets[d4.x], 1)] = s4.x;
        if ((unsigned)d4.y < (unsigned)N && (unsigned)s4.y < (unsigned)N)
            csr[atomicAdd(&offsets[d4.y], 1)] = s4.y;
        if ((unsigned)d4.z < (unsigned)N && (unsigned)s4.z < (unsigned)N)
            csr[atomicAdd(&offsets[d4.z], 1)] = s4.z;
        if ((unsigned)d4.w < (unsigned)N && (unsigned)s4.w < (unsigned)N)
            csr[atomicAdd(&offsets[d4.w], 1)] = s4.w;
    } else {
        for (int e = base; e < E; e++) {
            int d = dst_idx[e];
            int s = src_idx[e];
            if ((unsigned)d < (unsigned)N && (unsigned)s < (unsigned)N)
                csr[atomicAdd(&offsets[d], 1)] = s;
        }
    }
}

// 4) aggregate + finalize: ONE WARP per dest node.
//    Half-warp 0 sums even edges, half-warp 1 sums odd edges; each half's 16
//    lanes cover the 64-float row (one float4 per lane). Halves are combined
//    via shfl_down(16) and lanes 0-15 write the final row.
__global__ void __launch_bounds__(256) aggregate_kernel(
    const float* __restrict__ feat,
    const int* __restrict__ csr,
    const int* __restrict__ offsets,   // row ends
    const int* __restrict__ counts,    // degrees
    float* __restrict__ out,
    int N)
{
    int node = (blockIdx.x * blockDim.x + threadIdx.x) >> 5;
    if (node >= N) return;            // warp-uniform
    int lane  = threadIdx.x & 31;
    int half  = lane >> 4;            // 0 or 1
    int flane = lane & 15;
    size_t loff = (size_t)(flane * 4);

    int deg = counts[node];
    int end = offsets[node];
    int start = end - deg;

    float4 a0 = {0.f,0.f,0.f,0.f}, a1 = {0.f,0.f,0.f,0.f};

    int i = start + half;             // this half's first edge
    for (; i + 2 < end; i += 4) {     // edges i and i+2 (stride 2 per half)
        int s0 = csr[i];
        int s1 = csr[i + 2];
        float4 v0 = *reinterpret_cast<const float4*>(feat + (size_t)s0 * FEAT_DIM + loff);
        float4 v1 = *reinterpret_cast<const float4*>(feat + (size_t)s1 * FEAT_DIM + loff);
        a0.x += v0.x; a0.y += v0.y; a0.z += v0.z; a0.w += v0.w;
        a1.x += v1.x; a1.y += v1.y; a1.z += v1.z; a1.w += v1.w;
    }
    if (i < end) {
        int s0 = csr[i];
        float4 v0 = *reinterpret_cast<const float4*>(feat + (size_t)s0 * FEAT_DIM + loff);
        a0.x += v0.x; a0.y += v0.y; a0.z += v0.z; a0.w += v0.w;
    }

    a0.x += a1.x; a0.y += a1.y; a0.z += a1.z; a0.w += a1.w;

    // Combine halves: lane k gets lane k+16's partial.
    a0.x += __shfl_down_sync(0xFFFFFFFF, a0.x, 16);
    a0.y += __shfl_down_sync(0xFFFFFFFF, a0.y, 16);
    a0.z += __shfl_down_sync(0xFFFFFFFF, a0.z, 16);
    a0.w += __shfl_down_sync(0xFFFFFFFF, a0.w, 16);

    if (half == 0) {
        float4 f = *reinterpret_cast<const float4*>(feat + (size_t)node * FEAT_DIM + loff);
        float4 o;
        if (deg > 0) {
            float inv = 1.0f / (float)deg;
            o.x = 2.0f * f.x + a0.x * inv;
            o.y = 2.0f * f.y + a0.y * inv;
            o.z = 2.0f * f.z + a0.z * inv;
            o.w = 2.0f * f.w + a0.w * inv;
        } else {
            o = f;
        }
        *reinterpret_cast<float4*>(out + (size_t)node * FEAT_DIM + loff) = o;
    }
}

extern "C" void kernel_launch(void* const* d_in, const int* in_sizes, int n_in,
                              void* d_out, int out_size)
{
    const float* feat = (const float*)d_in[0];
    const int* edge_index = (const int*)d_in[1];   // int32 (JAX x64-disabled)

    int N = in_sizes[0] / FEAT_DIM;       // 100000
    int E = in_sizes[1] / 2;              // 1600000
    const int* src_idx = edge_index;
    const int* dst_idx = edge_index + E;

    float* out = (float*)d_out;

    void *counts_p, *offsets_p, *sums_p, *ctr_p, *csr_p;
    cudaGetSymbolAddress(&counts_p,  g_counts);
    cudaGetSymbolAddress(&offsets_p, g_offsets);
    cudaGetSymbolAddress(&sums_p,    g_sums);
    cudaGetSymbolAddress(&ctr_p,     g_ctr);
    cudaGetSymbolAddress(&csr_p,     g_csr);
    int* counts  = (int*)counts_p;
    int* offsets = (int*)offsets_p;
    int* sums    = (int*)sums_p;
    int* ctr     = (int*)ctr_p;
    int* csr     = (int*)csr_p;

    cudaMemsetAsync(counts, 0, (size_t)N * sizeof(int));
    cudaMemsetAsync(sums, 0, MAX_SCAN_BLOCKS * sizeof(int));
    cudaMemsetAsync(ctr, 0, sizeof(int));

    // 1) histogram (4 edges per thread)
    {
        int threads = (E + 3) / 4;
        hist_kernel<<<(threads + 255) / 256, 256>>>(dst_idx, counts, E, N);
    }

    // 2) single-kernel exclusive scan
    int nb = (N + SCAN_BLOCK - 1) / SCAN_BLOCK;   // 98
    scan_kernel<<<nb, SCAN_BLOCK>>>(counts, offsets, sums, ctr, N, nb);

    // 3) scatter src ids by dest (4 edges per thread)
    {
        int threads = (E + 3) / 4;
        scatter_kernel<<<(threads + 255) / 256, 256>>>(src_idx, dst_idx, offsets, csr, E, N);
    }

    // 4) aggregate + finalize: one warp per node
    {
        long long total = (long long)N * 32;
        int grid = (int)((total + 255) / 256);
        aggregate_kernel<<<grid, 256>>>(feat, csr, offsets, counts, out, N);
    }
}

// round 6
// speedup vs baseline: 1.1296x; 1.1011x over previous
#include <cuda_runtime.h>
#include <cstdint>

#define N_NODES_MAX 100000
#define E_MAX       1600000
#define FEAT_DIM    64
#define SCAN_BLOCK  1024
#define MAX_SCAN_BLOCKS 256

// All persistent state is self-maintaining: zero at program start (BSS) and
// restored to zero by the kernels themselves before each call completes.
__device__ int g_counts [N_NODES_MAX];          // in-degree (zeroed by aggregate)
__device__ int g_sums   [MAX_SCAN_BLOCKS];      // scan block totals (write-before-read)
__device__ int g_ctr    [2];                    // barrier counters (self-resetting)
__device__ int g_offsets[N_NODES_MAX];          // excl scan -> row ends after scatter
__device__ int g_csr    [E_MAX];                // src ids grouped by dest

// 1) histogram of destination indices (4 edges/thread, vectorized load)
__global__ void __launch_bounds__(256) hist_kernel(
    const int* __restrict__ dst_idx, int* __restrict__ counts, int E, int N)
{
    int i = blockIdx.x * blockDim.x + threadIdx.x;
    int base = i * 4;
    if (base + 3 < E) {
        int4 d4 = *reinterpret_cast<const int4*>(dst_idx + base);
        if ((unsigned)d4.x < (unsigned)N) atomicAdd(&counts[d4.x], 1);
        if ((unsigned)d4.y < (unsigned)N) atomicAdd(&counts[d4.y], 1);
        if ((unsigned)d4.z < (unsigned)N) atomicAdd(&counts[d4.z], 1);
        if ((unsigned)d4.w < (unsigned)N) atomicAdd(&counts[d4.w], 1);
    } else {
        for (int e = base; e < E; e++) {
            int d = dst_idx[e];
            if ((unsigned)d < (unsigned)N) atomicAdd(&counts[d], 1);
        }
    }
}

// 2) single-kernel global exclusive scan (all 98 blocks co-resident).
//    Barrier counters self-reset: last block through resets both to 0.
__global__ void __launch_bounds__(SCAN_BLOCK) scan_kernel(
    const int* __restrict__ counts, int* __restrict__ offsets,
    int* __restrict__ sums, int* __restrict__ ctr, int n, int nb)
{
    __shared__ int sh[SCAN_BLOCK];
    __shared__ int s_base;
    int tid = threadIdx.x;
    int i = blockIdx.x * SCAN_BLOCK + tid;
    int v = (i < n) ? counts[i] : 0;
    sh[tid] = v;
    __syncthreads();
    #pragma unroll
    for (int off = 1; off < SCAN_BLOCK; off <<= 1) {
        int t = (tid >= off) ? sh[tid - off] : 0;
        __syncthreads();
        sh[tid] += t;
        __syncthreads();
    }
    int incl = sh[tid];

    // Publish block total; wait for all blocks.
    if (tid == SCAN_BLOCK - 1) {
        sums[blockIdx.x] = incl;
        __threadfence();
        atomicAdd(&ctr[0], 1);
    }
    if (tid == 0) {
        while (atomicAdd(&ctr[0], 0) < nb) { }
    }
    __syncthreads();
    __threadfence();

    // Warp 0: base = sum of preceding block totals.
    if (tid < 32) {
        int b = 0;
        for (int j = tid; j < blockIdx.x; j += 32) b += sums[j];
        #pragma unroll
        for (int o = 16; o > 0; o >>= 1)
            b += __shfl_down_sync(0xFFFFFFFF, b, o);
        if (tid == 0) s_base = b;
    }
    __syncthreads();

    if (i < n) offsets[i] = s_base + incl - v;

    // Self-reset: the last block to finish resets both counters for next call.
    if (tid == 0) {
        int done = atomicAdd(&ctr[1], 1) + 1;
        if (done == nb) {
            ctr[0] = 0;
            ctr[1] = 0;
            __threadfence();
        }
    }
}

// 3) scatter src ids into CSR, 4 edges/thread (offsets become row ends)
__global__ void __launch_bounds__(256) scatter_kernel(
    const int* __restrict__ src_idx, const int* __restrict__ dst_idx,
    int* __restrict__ offsets, int* __restrict__ csr, int E, int N)
{
    int i = blockIdx.x * blockDim.x + threadIdx.x;
    int base = i * 4;
    if (base + 3 < E) {
        int4 s4 = *reinterpret_cast<const int4*>(src_idx + base);
        int4 d4 = *reinterpret_cast<const int4*>(dst_idx + base);
        if ((unsigned)d4.x < (unsigned)N && (unsigned)s4.x < (unsigned)N)
            csr[atomicAdd(&offsets[d4.x], 1)] = s4.x;
        if ((unsigned)d4.y < (unsigned)N && (unsigned)s4.y < (unsigned)N)
            csr[atomicAdd(&offsets[d4.y], 1)] = s4.y;
        if ((unsigned)d4.z < (unsigned)N && (unsigned)s4.z < (unsigned)N)
            csr[atomicAdd(&offsets[d4.z], 1)] = s4.z;
        if ((unsigned)d4.w < (unsigned)N && (unsigned)s4.w < (unsigned)N)
            csr[atomicAdd(&offsets[d4.w], 1)] = s4.w;
    } else {
        for (int e = base; e < E; e++) {
            int d = dst_idx[e];
            int s = src_idx[e];
            if ((unsigned)d < (unsigned)N && (unsigned)s < (unsigned)N)
                csr[atomicAdd(&offsets[d], 1)] = s;
        }
    }
}

// 4) aggregate + finalize: one warp per dest node.
//    Preload up to 32 csr indices (one per lane), then shfl them into the
//    gather loop -> feat gathers never wait on csr loads. Half-warp 0 takes
//    even edges, half-warp 1 odd edges; 4 independent gathers in flight per
//    half. Combine halves via shfl_down(16). Lane 0 zeroes counts[node] for
//    the next invocation.
__global__ void __launch_bounds__(256) aggregate_kernel(
    const float* __restrict__ feat,
    const int* __restrict__ csr,
    const int* __restrict__ offsets,   // row ends
    int* __restrict__ counts,          // degrees (zeroed on exit)
    float* __restrict__ out,
    int N)
{
    int node = (blockIdx.x * blockDim.x + threadIdx.x) >> 5;
    if (node >= N) return;            // warp-uniform
    int lane  = threadIdx.x & 31;
    int half  = lane >> 4;            // 0 or 1
    int flane = lane & 15;
    size_t loff = (size_t)(flane * 4);

    int deg = counts[node];
    int end = offsets[node];
    int start = end - deg;
    int m = deg < 32 ? deg : 32;

    // Preload first m csr indices, one per lane (coalesced).
    int idx = 0;
    if (lane < m) idx = csr[start + lane];

    float4 a0 = {0.f,0.f,0.f,0.f}, a1 = {0.f,0.f,0.f,0.f};

    // Main loop: warp-uniform bound, indices via shfl, 4 gathers/half in flight.
    int jb = 0;
    for (; jb + 8 <= m; jb += 8) {
        int j = jb + half;
        int s0 = __shfl_sync(0xFFFFFFFF, idx, j);
        int s1 = __shfl_sync(0xFFFFFFFF, idx, j + 2);
        int s2 = __shfl_sync(0xFFFFFFFF, idx, j + 4);
        int s3 = __shfl_sync(0xFFFFFFFF, idx, j + 6);
        float4 v0 = *reinterpret_cast<const float4*>(feat + (size_t)s0 * FEAT_DIM + loff);
        float4 v1 = *reinterpret_cast<const float4*>(feat + (size_t)s1 * FEAT_DIM + loff);
        float4 v2 = *reinterpret_cast<const float4*>(feat + (size_t)s2 * FEAT_DIM + loff);
        float4 v3 = *reinterpret_cast<const float4*>(feat + (size_t)s3 * FEAT_DIM + loff);
        a0.x += v0.x; a0.y += v0.y; a0.z += v0.z; a0.w += v0.w;
        a1.x += v1.x; a1.y += v1.y; a1.z += v1.z; a1.w += v1.w;
        a0.x += v2.x; a0.y += v2.y; a0.z += v2.z; a0.w += v2.w;
        a1.x += v3.x; a1.y += v3.y; a1.z += v3.z; a1.w += v3.w;
    }
    // Remainder inside the preloaded window (parity-divergent: direct loads).
    for (int j = jb + half; j < m; j += 2) {
        int s = csr[start + j];
        float4 v = *reinterpret_cast<const float4*>(feat + (size_t)s * FEAT_DIM + loff);
        a0.x += v.x; a0.y += v.y; a0.z += v.z; a0.w += v.w;
    }
    // Rare tail: deg > 32.
    for (int i = start + 32 + half; i < end; i += 2) {
        int s = csr[i];
        float4 v = *reinterpret_cast<const float4*>(feat + (size_t)s * FEAT_DIM + loff);
        a1.x += v.x; a1.y += v.y; a1.z += v.z; a1.w += v.w;
    }

    a0.x += a1.x; a0.y += a1.y; a0.z += a1.z; a0.w += a1.w;

    // Combine halves: lane k gets lane k+16's partial.
    a0.x += __shfl_down_sync(0xFFFFFFFF, a0.x, 16);
    a0.y += __shfl_down_sync(0xFFFFFFFF, a0.y, 16);
    a0.z += __shfl_down_sync(0xFFFFFFFF, a0.z, 16);
    a0.w += __shfl_down_sync(0xFFFFFFFF, a0.w, 16);

    if (half == 0) {
        float4 f = *reinterpret_cast<const float4*>(feat + (size_t)node * FEAT_DIM + loff);
        float4 o;
        if (deg > 0) {
            float inv = 1.0f / (float)deg;
            o.x = 2.0f * f.x + a0.x * inv;
            o.y = 2.0f * f.y + a0.y * inv;
            o.z = 2.0f * f.z + a0.z * inv;
            o.w = 2.0f * f.w + a0.w * inv;
        } else {
            o = f;
        }
        *reinterpret_cast<float4*>(out + (size_t)node * FEAT_DIM + loff) = o;
    }

    // Leave counts zeroed for the next invocation (replaces a memset).
    if (lane == 0) counts[node] = 0;
}

extern "C" void kernel_launch(void* const* d_in, const int* in_sizes, int n_in,
                              void* d_out, int out_size)
{
    const float* feat = (const float*)d_in[0];
    const int* edge_index = (const int*)d_in[1];   // int32 (JAX x64-disabled)

    int N = in_sizes[0] / FEAT_DIM;       // 100000
    int E = in_sizes[1] / 2;              // 1600000
    const int* src_idx = edge_index;
    const int* dst_idx = edge_index + E;

    float* out = (float*)d_out;

    void *counts_p, *offsets_p, *sums_p, *ctr_p, *csr_p;
    cudaGetSymbolAddress(&counts_p,  g_counts);
    cudaGetSymbolAddress(&offsets_p, g_offsets);
    cudaGetSymbolAddress(&sums_p,    g_sums);
    cudaGetSymbolAddress(&ctr_p,     g_ctr);
    cudaGetSymbolAddress(&csr_p,     g_csr);
    int* counts  = (int*)counts_p;
    int* offsets = (int*)offsets_p;
    int* sums    = (int*)sums_p;
    int* ctr     = (int*)ctr_p;
    int* csr     = (int*)csr_p;

    // No memsets: counts zeroed by previous aggregate (BSS-zero initially),
    // scan counters self-reset, sums write-before-read.

    // 1) histogram (4 edges per thread)
    {
        int threads = (E + 3) / 4;
        hist_kernel<<<(threads + 255) / 256, 256>>>(dst_idx, counts, E, N);
    }

    // 2) single-kernel exclusive scan
    int nb = (N + SCAN_BLOCK - 1) / SCAN_BLOCK;   // 98
    scan_kernel<<<nb, SCAN_BLOCK>>>(counts, offsets, sums, ctr, N, nb);

    // 3) scatter src ids by dest (4 edges per thread)
    {
        int threads = (E + 3) / 4;
        scatter_kernel<<<(threads + 255) / 256, 256>>>(src_idx, dst_idx, offsets, csr, E, N);
    }

    // 4) aggregate + finalize: one warp per node
    {
        long long total = (long long)N * 32;
        int grid = (int)((total + 255) / 256);
        aggregate_kernel<<<grid, 256>>>(feat, csr, offsets, counts, out, N);
    }
}